// round 1
// baseline (speedup 1.0000x reference)
#include <cuda_runtime.h>

#define N_NODES 100000
#define DEG     16
#define E_EDGES (N_NODES * DEG)
#define ALPHA   0.2f

// Scratch (static __device__ — no allocs allowed)
__device__ float  g_h   [(size_t)N_NODES * 128];   // [h_high(64) | h_low(64)] per node
__device__ float  g_hagg[(size_t)N_NODES * 128];   // [hagg_high | hagg_low]   per node
__device__ float4 g_scal[N_NODES];                 // (ssrc_h, sdst_h, ssrc_l, sdst_l)

// ---------------------------------------------------------------------------
// K1: h[N,128] = input[N,128] @ [W_high | W_low]  (fp32, smem-tiled)
// Block: 256 threads, tile = 64 nodes x 128 cols. W (64KB) + A tile (32KB) smem.
// ---------------------------------------------------------------------------
__global__ __launch_bounds__(256, 2)
void k_gemm(const float* __restrict__ A,
            const float* __restrict__ Wh,
            const float* __restrict__ Wl)
{
    extern __shared__ float sm[];
    float* Ws = sm;              // 128 x 128, row-major (k, c)
    float* As = sm + 128 * 128;  // 64  x 128, row-major (node, k)

    const int tid = threadIdx.x;
    const int nodeBase = blockIdx.x * 64;

    // Load W: cols [0,64) from W_high[128,64], cols [64,128) from W_low
    for (int i = tid; i < 128 * 64; i += 256) {
        int k = i >> 6, c = i & 63;
        Ws[k * 128 + c]      = Wh[i];
        Ws[k * 128 + 64 + c] = Wl[i];
    }
    // Load A tile (64 x 128), float4 coalesced, zero-pad past N
    for (int i = tid * 4; i < 64 * 128; i += 256 * 4) {
        int node = nodeBase + (i >> 7);
        float4 v = make_float4(0.f, 0.f, 0.f, 0.f);
        if (node < N_NODES)
            v = *(const float4*)(A + (size_t)node * 128 + (i & 127));
        *(float4*)(As + i) = v;
    }
    __syncthreads();

    const int tx = tid & 31;   // col group: cols [4*tx, 4*tx+4)
    const int ty = tid >> 5;   // node group: nodes [8*ty, 8*ty+8)

    float acc[8][4];
#pragma unroll
    for (int n = 0; n < 8; n++)
#pragma unroll
        for (int c = 0; c < 4; c++) acc[n][c] = 0.f;

    const float* arow = As + ty * 8 * 128;
#pragma unroll 4
    for (int k = 0; k < 128; k++) {
        float4 w = *(const float4*)(Ws + k * 128 + tx * 4);
#pragma unroll
        for (int n = 0; n < 8; n++) {
            float a = arow[n * 128 + k];   // broadcast within warp (same ty)
            acc[n][0] += a * w.x;
            acc[n][1] += a * w.y;
            acc[n][2] += a * w.z;
            acc[n][3] += a * w.w;
        }
    }

#pragma unroll
    for (int n = 0; n < 8; n++) {
        int node = nodeBase + ty * 8 + n;
        if (node < N_NODES)
            *(float4*)(g_h + (size_t)node * 128 + tx * 4) =
                make_float4(acc[n][0], acc[n][1], acc[n][2], acc[n][3]);
    }
}

// ---------------------------------------------------------------------------
// K2: per-node warp. hagg_high = 16*h_hi[i] + sum_e h_hi[dst_e]
//                    hagg_low  = 16*h_lo[i] - sum_e h_lo[dst_e]
// Also computes attention scalars scal[i] = (ssrc_h, sdst_h, ssrc_l, sdst_l).
// ---------------------------------------------------------------------------
__global__ __launch_bounds__(256)
void k_agg(const int* __restrict__ dst_arr,
           const float* __restrict__ a_high,
           const float* __restrict__ a_low)
{
    const int warp = (blockIdx.x * blockDim.x + threadIdx.x) >> 5;
    const int lane = threadIdx.x & 31;
    if (warp >= N_NODES) return;
    const int i = warp;
    const unsigned FULL = 0xffffffffu;

    int d = 0;
    if (lane < DEG) d = dst_arr[i * DEG + lane];

    float4 self = *(const float4*)(g_h + (size_t)i * 128 + lane * 4);

    float4 s = make_float4(0.f, 0.f, 0.f, 0.f);
#pragma unroll
    for (int e = 0; e < DEG; e++) {
        int de = __shfl_sync(FULL, d, e);
        float4 v = *(const float4*)(g_h + (size_t)de * 128 + lane * 4);
        s.x += v.x; s.y += v.y; s.z += v.z; s.w += v.w;
    }

    float sgn = (lane < 16) ? 1.f : -1.f;
    float4 o;
    o.x = 16.f * self.x + sgn * s.x;
    o.y = 16.f * self.y + sgn * s.y;
    o.z = 16.f * self.z + sgn * s.z;
    o.w = 16.f * self.w + sgn * s.w;
    *(float4*)(g_hagg + (size_t)i * 128 + lane * 4) = o;

    // Attention scalars: lanes<16 handle high half (a_high), lanes>=16 low half.
    const float* av = (lane < 16) ? a_high : a_low;
    const int j = (lane & 15) * 4;
    float4 a0 = *(const float4*)(av + j);
    float4 a1 = *(const float4*)(av + 64 + j);
    float p0 = self.x * a0.x + self.y * a0.y + self.z * a0.z + self.w * a0.w;
    float p1 = self.x * a1.x + self.y * a1.y + self.z * a1.z + self.w * a1.w;
#pragma unroll
    for (int off = 8; off; off >>= 1) {
        p0 += __shfl_xor_sync(FULL, p0, off);
        p1 += __shfl_xor_sync(FULL, p1, off);
    }
    float q0 = __shfl_sync(FULL, p0, 0);    // ssrc_h
    float q1 = __shfl_sync(FULL, p1, 0);    // sdst_h
    float q2 = __shfl_sync(FULL, p0, 16);   // ssrc_l
    float q3 = __shfl_sync(FULL, p1, 16);   // sdst_l
    if (lane == 0) g_scal[i] = make_float4(q0, q1, q2, q3);
}

// ---------------------------------------------------------------------------
// K3: per-node warp. Recompute e = exp(-leaky(s)), raw rowsums, relu6-clamped
// weights, gather-weight hagg[dst], combine halves, relu6 output.
// ---------------------------------------------------------------------------
__global__ __launch_bounds__(256)
void k_out(const int* __restrict__ dst_arr, float* __restrict__ out)
{
    const int warp = (blockIdx.x * blockDim.x + threadIdx.x) >> 5;
    const int lane = threadIdx.x & 31;
    if (warp >= N_NODES) return;
    const int i = warp;
    const unsigned FULL = 0xffffffffu;

    int d = 0;
    if (lane < DEG) d = dst_arr[i * DEG + lane];

    float4 si = g_scal[i];   // broadcast load (all lanes same addr)

    float eh = 0.f, el = 0.f;
    if (lane < DEG) {
        float4 sd = g_scal[d];
        float sh = si.x + sd.y;              // ssrc_h[i] + sdst_h[d]
        float sl = si.z + sd.w;              // ssrc_l[i] + sdst_l[d]
        float lh = sh > 0.f ? sh : ALPHA * sh;
        float ll = sl > 0.f ? sl : ALPHA * sl;
        eh = __expf(-lh);
        el = __expf(-ll);
    }

    // Raw rowsums over the 16 edge lanes
    float rh = eh, rl = el;
#pragma unroll
    for (int off = 8; off; off >>= 1) {
        rh += __shfl_xor_sync(FULL, rh, off);
        rl += __shfl_xor_sync(FULL, rl, off);
    }
    rh = __shfl_sync(FULL, rh, 0);
    rl = __shfl_sync(FULL, rl, 0);

    // relu6-clamped weights (e > 0 always -> just min with 6)
    float ehc = fminf(eh, 6.f);
    float elc = fminf(el, 6.f);

    float4 acc = make_float4(0.f, 0.f, 0.f, 0.f);
#pragma unroll
    for (int e = 0; e < DEG; e++) {
        int   de = __shfl_sync(FULL, d,   e);
        float wh = __shfl_sync(FULL, ehc, e);
        float wl = __shfl_sync(FULL, elc, e);
        float w  = (lane < 16) ? wh : wl;
        float4 v = *(const float4*)(g_hagg + (size_t)de * 128 + lane * 4);
        acc.x += w * v.x; acc.y += w * v.y; acc.z += w * v.z; acc.w += w * v.w;
    }

    // Combine high (lanes 0..15) with low (lanes 16..31, same columns)
    float lx = __shfl_xor_sync(FULL, acc.x, 16);
    float ly = __shfl_xor_sync(FULL, acc.y, 16);
    float lz = __shfl_xor_sync(FULL, acc.z, 16);
    float lw = __shfl_xor_sync(FULL, acc.w, 16);

    if (lane < 16) {
        float irh = 1.f / rh, irl = 1.f / rl;
        float4 r;
        r.x = 0.5f * (acc.x * irh + lx * irl);
        r.y = 0.5f * (acc.y * irh + ly * irl);
        r.z = 0.5f * (acc.z * irh + lz * irl);
        r.w = 0.5f * (acc.w * irh + lw * irl);
        r.x = fminf(fmaxf(r.x, 0.f), 6.f);
        r.y = fminf(fmaxf(r.y, 0.f), 6.f);
        r.z = fminf(fmaxf(r.z, 0.f), 6.f);
        r.w = fminf(fmaxf(r.w, 0.f), 6.f);
        *(float4*)(out + (size_t)i * 64 + lane * 4) = r;
    }
}

// ---------------------------------------------------------------------------
extern "C" void kernel_launch(void* const* d_in, const int* in_sizes, int n_in,
                              void* d_out, int out_size)
{
    const float* input = (const float*)d_in[0];
    const int*   edge  = (const int*)  d_in[1];   // [2, E]: src then dst
    const float* Wh    = (const float*)d_in[2];
    const float* Wl    = (const float*)d_in[3];
    const float* ah    = (const float*)d_in[4];
    const float* al    = (const float*)d_in[5];
    float* out = (float*)d_out;

    const int* dst = edge + E_EDGES;

    const int SMEM_K1 = (128 * 128 + 64 * 128) * (int)sizeof(float);  // 98304 B
    cudaFuncSetAttribute(k_gemm, cudaFuncAttributeMaxDynamicSharedMemorySize, SMEM_K1);

    const int gemmBlocks = (N_NODES + 63) / 64;
    k_gemm<<<gemmBlocks, 256, SMEM_K1>>>(input, Wh, Wl);

    const int warpBlocks = (N_NODES + 7) / 8;  // 8 warps per 256-thread block
    k_agg<<<warpBlocks, 256>>>(dst, ah, al);
    k_out<<<warpBlocks, 256>>>(dst, out);
}

// round 3
// speedup vs baseline: 1.1733x; 1.1733x over previous
#include <cuda_runtime.h>
#include <cuda_bf16.h>
#include <cstdint>

#define N_NODES 100000
#define DEG     16
#define E_EDGES (N_NODES * DEG)
#define ALPHA   0.2f

// Scratch (static __device__ — no allocs allowed)
__device__ float  g_h   [(size_t)N_NODES * 128];   // [h_high(64) | h_low(64)] per node
__device__ float  g_hagg[(size_t)N_NODES * 128];   // [hagg_high | hagg_low]   per node
__device__ float4 g_scal[N_NODES];                 // (ssrc_h, sdst_h, ssrc_l, sdst_l)
// W as B-operand [n=128][k=128] bf16 hi/lo, chunk-swizzled (ldmatrix-ready)
__device__ uint32_t g_Wblk_hi[8192];               // 32768 bytes
__device__ uint32_t g_Wblk_lo[8192];

// Swizzled byte offset in a [row][k] bf16 tile with 256B rows (128 k per row).
// 16B chunk index (k>>3) XORed with (row&7) -> conflict-free ldmatrix.
__device__ __forceinline__ uint32_t sw_off(int row, int k) {
    return (uint32_t)(row * 256 + ((((k >> 3) ^ (row & 7)) << 4) | ((k & 7) << 1)));
}

__device__ __forceinline__ uint32_t smem_u32(const void* p) {
    uint32_t a;
    asm("{ .reg .u64 t; cvta.to.shared.u64 t, %1; cvt.u32.u64 %0, t; }" : "=r"(a) : "l"(p));
    return a;
}

__device__ __forceinline__ void ldmatrix_x4(uint32_t* r, uint32_t addr) {
    asm volatile("ldmatrix.sync.aligned.m8n8.x4.shared.b16 {%0,%1,%2,%3}, [%4];"
                 : "=r"(r[0]), "=r"(r[1]), "=r"(r[2]), "=r"(r[3]) : "r"(addr));
}

__device__ __forceinline__ void mma_bf16(float* c, const uint32_t* a, uint32_t b0, uint32_t b1) {
    asm volatile(
        "mma.sync.aligned.m16n8k16.row.col.f32.bf16.bf16.f32 "
        "{%0,%1,%2,%3}, {%4,%5,%6,%7}, {%8,%9}, {%0,%1,%2,%3};"
        : "+f"(c[0]), "+f"(c[1]), "+f"(c[2]), "+f"(c[3])
        : "r"(a[0]), "r"(a[1]), "r"(a[2]), "r"(a[3]), "r"(b0), "r"(b1));
}

// ---------------------------------------------------------------------------
// K0: bake Wcat as B-operand [n][k] bf16 hi/lo, swizzled. B[n][k] = Wcat[k][n].
// ---------------------------------------------------------------------------
__global__ void k_wprep(const float* __restrict__ Wh, const float* __restrict__ Wl)
{
    int idx = blockIdx.x * blockDim.x + threadIdx.x;
    if (idx >= 128 * 64) return;
    int n = idx >> 6, kp = idx & 63, k = kp * 2;
    const float* Ws = (n < 64) ? Wh : Wl;
    int c = n & 63;
    float w0 = Ws[k * 64 + c];
    float w1 = Ws[(k + 1) * 64 + c];

    __nv_bfloat16 h0 = __float2bfloat16_rn(w0);
    __nv_bfloat16 h1 = __float2bfloat16_rn(w1);
    __nv_bfloat16 l0 = __float2bfloat16_rn(w0 - __bfloat162float(h0));
    __nv_bfloat16 l1 = __float2bfloat16_rn(w1 - __bfloat162float(h1));

    uint32_t hp = ((uint32_t)__bfloat16_as_ushort(h1) << 16) | __bfloat16_as_ushort(h0);
    uint32_t lp = ((uint32_t)__bfloat16_as_ushort(l1) << 16) | __bfloat16_as_ushort(l0);

    uint32_t off = sw_off(n, k);
    *(uint32_t*)((char*)g_Wblk_hi + off) = hp;
    *(uint32_t*)((char*)g_Wblk_lo + off) = lp;
}

// ---------------------------------------------------------------------------
// K1: mma.sync bf16 split GEMM. C[128x128] = A_tile @ Wcat (3 HMMA passes).
// smem: Ahi@0 (32KB), Alo@32K, Whi@64K, Wlo@96K  -> 128KB dynamic
// ---------------------------------------------------------------------------
#define SM_AHI 0
#define SM_ALO 32768
#define SM_WHI 65536
#define SM_WLO 98304
#define SM_TOTAL 131072

__global__ __launch_bounds__(256, 1)
void k_gemm_mma(const float* __restrict__ A)
{
    extern __shared__ char smem[];
    const uint32_t sbase = smem_u32(smem);
    const int tid = threadIdx.x;
    const int wid = tid >> 5;
    const int lane = tid & 31;
    const int rowBase = blockIdx.x * 128;

    // Copy pre-baked W (already bf16 + swizzled): verbatim uint4 copies
    {
        const uint4* shi = (const uint4*)g_Wblk_hi;
        const uint4* slo = (const uint4*)g_Wblk_lo;
        uint4* dhi = (uint4*)(smem + SM_WHI);
        uint4* dlo = (uint4*)(smem + SM_WLO);
#pragma unroll
        for (int i = tid; i < 2048; i += 256) { dhi[i] = shi[i]; dlo[i] = slo[i]; }
    }

    // Load A tile fp32 (coalesced float2), split bf16 hi/lo, store swizzled
    for (int i = tid; i < 8192; i += 256) {
        int r = i >> 6, kp = i & 63, k = kp * 2;
        int node = rowBase + r;
        float2 v = make_float2(0.f, 0.f);
        if (node < N_NODES) v = *(const float2*)(A + (size_t)node * 128 + k);

        __nv_bfloat16 h0 = __float2bfloat16_rn(v.x);
        __nv_bfloat16 h1 = __float2bfloat16_rn(v.y);
        __nv_bfloat16 l0 = __float2bfloat16_rn(v.x - __bfloat162float(h0));
        __nv_bfloat16 l1 = __float2bfloat16_rn(v.y - __bfloat162float(h1));
        uint32_t hp = ((uint32_t)__bfloat16_as_ushort(h1) << 16) | __bfloat16_as_ushort(h0);
        uint32_t lp = ((uint32_t)__bfloat16_as_ushort(l1) << 16) | __bfloat16_as_ushort(l0);

        uint32_t off = sw_off(r, k);
        *(uint32_t*)(smem + SM_AHI + off) = hp;
        *(uint32_t*)(smem + SM_ALO + off) = lp;
    }
    __syncthreads();

    const int m_base = wid * 16;
    float c[16][4];
#pragma unroll
    for (int j = 0; j < 16; j++)
#pragma unroll
        for (int q = 0; q < 4; q++) c[j][q] = 0.f;

    const int g  = lane >> 3;      // ldmatrix lane group
    const int rr = lane & 7;
    // A frag address pieces: row_off = (g&1)*8 + rr, k_off = (g>>1)*8
    const int a_row = m_base + ((g & 1) << 3) + rr;
    const int a_kof = (g >> 1) << 3;
    // B frag address pieces: n_off = (g>>1)*8 + rr, k_off = (g&1)*8
    const int b_nof = ((g >> 1) << 3) + rr;
    const int b_kof = (g & 1) << 3;

#pragma unroll
    for (int pass = 0; pass < 3; pass++) {
        const uint32_t aBase = sbase + ((pass == 2) ? SM_ALO : SM_AHI);
        const uint32_t bBase = sbase + ((pass == 1) ? SM_WLO : SM_WHI);
#pragma unroll
        for (int ks = 0; ks < 8; ks++) {
            const int kb = ks * 16;
            uint32_t a[4];
            ldmatrix_x4(a, aBase + sw_off(a_row, kb + a_kof));
#pragma unroll
            for (int nt = 0; nt < 8; nt++) {
                uint32_t b[4];
                ldmatrix_x4(b, bBase + sw_off(nt * 16 + b_nof, kb + b_kof));
                mma_bf16(c[2 * nt],     a, b[0], b[1]);
                mma_bf16(c[2 * nt + 1], a, b[2], b[3]);
            }
        }
    }

    // Writeout: thread holds (row0, row0+8) x (col pairs) per ntile
    const int row0 = rowBase + m_base + (lane >> 2);
    const int cb   = (lane & 3) * 2;
    if (row0 < N_NODES) {
        float* o = g_h + (size_t)row0 * 128;
#pragma unroll
        for (int j = 0; j < 16; j++)
            *(float2*)(o + j * 8 + cb) = make_float2(c[j][0], c[j][1]);
    }
    if (row0 + 8 < N_NODES) {
        float* o = g_h + (size_t)(row0 + 8) * 128;
#pragma unroll
        for (int j = 0; j < 16; j++)
            *(float2*)(o + j * 8 + cb) = make_float2(c[j][2], c[j][3]);
    }
}

// ---------------------------------------------------------------------------
// K2: per-node warp aggregation + attention scalars
// ---------------------------------------------------------------------------
__global__ __launch_bounds__(256)
void k_agg(const int* __restrict__ dst_arr,
           const float* __restrict__ a_high,
           const float* __restrict__ a_low)
{
    const int warp = (blockIdx.x * blockDim.x + threadIdx.x) >> 5;
    const int lane = threadIdx.x & 31;
    if (warp >= N_NODES) return;
    const int i = warp;
    const unsigned FULL = 0xffffffffu;

    int d = 0;
    if (lane < DEG) d = dst_arr[i * DEG + lane];

    float4 self = *(const float4*)(g_h + (size_t)i * 128 + lane * 4);

    float4 s = make_float4(0.f, 0.f, 0.f, 0.f);
#pragma unroll
    for (int e = 0; e < DEG; e++) {
        int de = __shfl_sync(FULL, d, e);
        float4 v = *(const float4*)(g_h + (size_t)de * 128 + lane * 4);
        s.x += v.x; s.y += v.y; s.z += v.z; s.w += v.w;
    }

    float sgn = (lane < 16) ? 1.f : -1.f;
    float4 o;
    o.x = 16.f * self.x + sgn * s.x;
    o.y = 16.f * self.y + sgn * s.y;
    o.z = 16.f * self.z + sgn * s.z;
    o.w = 16.f * self.w + sgn * s.w;
    *(float4*)(g_hagg + (size_t)i * 128 + lane * 4) = o;

    const float* av = (lane < 16) ? a_high : a_low;
    const int j = (lane & 15) * 4;
    float4 a0 = *(const float4*)(av + j);
    float4 a1 = *(const float4*)(av + 64 + j);
    float p0 = self.x * a0.x + self.y * a0.y + self.z * a0.z + self.w * a0.w;
    float p1 = self.x * a1.x + self.y * a1.y + self.z * a1.z + self.w * a1.w;
#pragma unroll
    for (int off = 8; off; off >>= 1) {
        p0 += __shfl_xor_sync(FULL, p0, off);
        p1 += __shfl_xor_sync(FULL, p1, off);
    }
    float q0 = __shfl_sync(FULL, p0, 0);
    float q1 = __shfl_sync(FULL, p1, 0);
    float q2 = __shfl_sync(FULL, p0, 16);
    float q3 = __shfl_sync(FULL, p1, 16);
    if (lane == 0) g_scal[i] = make_float4(q0, q1, q2, q3);
}

// ---------------------------------------------------------------------------
// K3: weighting + output
// ---------------------------------------------------------------------------
__global__ __launch_bounds__(256)
void k_out(const int* __restrict__ dst_arr, float* __restrict__ out)
{
    const int warp = (blockIdx.x * blockDim.x + threadIdx.x) >> 5;
    const int lane = threadIdx.x & 31;
    if (warp >= N_NODES) return;
    const int i = warp;
    const unsigned FULL = 0xffffffffu;

    int d = 0;
    if (lane < DEG) d = dst_arr[i * DEG + lane];

    float4 si = g_scal[i];

    float eh = 0.f, el = 0.f;
    if (lane < DEG) {
        float4 sd = g_scal[d];
        float sh = si.x + sd.y;
        float sl = si.z + sd.w;
        float lh = sh > 0.f ? sh : ALPHA * sh;
        float ll = sl > 0.f ? sl : ALPHA * sl;
        eh = __expf(-lh);
        el = __expf(-ll);
    }

    float rh = eh, rl = el;
#pragma unroll
    for (int off = 8; off; off >>= 1) {
        rh += __shfl_xor_sync(FULL, rh, off);
        rl += __shfl_xor_sync(FULL, rl, off);
    }
    rh = __shfl_sync(FULL, rh, 0);
    rl = __shfl_sync(FULL, rl, 0);

    float ehc = fminf(eh, 6.f);
    float elc = fminf(el, 6.f);

    float4 acc = make_float4(0.f, 0.f, 0.f, 0.f);
#pragma unroll
    for (int e = 0; e < DEG; e++) {
        int   de = __shfl_sync(FULL, d,   e);
        float wh = __shfl_sync(FULL, ehc, e);
        float wl = __shfl_sync(FULL, elc, e);
        float w  = (lane < 16) ? wh : wl;
        float4 v = *(const float4*)(g_hagg + (size_t)de * 128 + lane * 4);
        acc.x += w * v.x; acc.y += w * v.y; acc.z += w * v.z; acc.w += w * v.w;
    }

    float lx = __shfl_xor_sync(FULL, acc.x, 16);
    float ly = __shfl_xor_sync(FULL, acc.y, 16);
    float lz = __shfl_xor_sync(FULL, acc.z, 16);
    float lw = __shfl_xor_sync(FULL, acc.w, 16);

    if (lane < 16) {
        float irh = 1.f / rh, irl = 1.f / rl;
        float4 r;
        r.x = 0.5f * (acc.x * irh + lx * irl);
        r.y = 0.5f * (acc.y * irh + ly * irl);
        r.z = 0.5f * (acc.z * irh + lz * irl);
        r.w = 0.5f * (acc.w * irh + lw * irl);
        r.x = fminf(fmaxf(r.x, 0.f), 6.f);
        r.y = fminf(fmaxf(r.y, 0.f), 6.f);
        r.z = fminf(fmaxf(r.z, 0.f), 6.f);
        r.w = fminf(fmaxf(r.w, 0.f), 6.f);
        *(float4*)(out + (size_t)i * 64 + lane * 4) = r;
    }
}

// ---------------------------------------------------------------------------
extern "C" void kernel_launch(void* const* d_in, const int* in_sizes, int n_in,
                              void* d_out, int out_size)
{
    const float* input = (const float*)d_in[0];
    const int*   edge  = (const int*)  d_in[1];
    const float* Wh    = (const float*)d_in[2];
    const float* Wl    = (const float*)d_in[3];
    const float* ah    = (const float*)d_in[4];
    const float* al    = (const float*)d_in[5];
    float* out = (float*)d_out;

    const int* dst = edge + E_EDGES;

    cudaFuncSetAttribute(k_gemm_mma, cudaFuncAttributeMaxDynamicSharedMemorySize, SM_TOTAL);

    k_wprep<<<32, 256>>>(Wh, Wl);

    const int gemmBlocks = (N_NODES + 127) / 128;   // 782
    k_gemm_mma<<<gemmBlocks, 256, SM_TOTAL>>>(input);

    const int warpBlocks = (N_NODES + 7) / 8;
    k_agg<<<warpBlocks, 256>>>(dst, ah, al);
    k_out<<<warpBlocks, 256>>>(dst, out);
}

// round 4
// speedup vs baseline: 1.1863x; 1.0111x over previous
#include <cuda_runtime.h>
#include <cuda_bf16.h>
#include <cstdint>

#define N_NODES 100000
#define DEG     16
#define E_EDGES (N_NODES * DEG)
#define ALPHA   0.2f

// Scratch (static __device__ — no allocs allowed)
__device__ float  g_h   [(size_t)N_NODES * 128];   // [h_high(64) | h_low(64)] per node
__device__ float  g_hagg[(size_t)N_NODES * 128];   // [hagg_high | hagg_low]   per node
__device__ float2 g_ssrc[N_NODES];                 // (ssrc_h, ssrc_l)
__device__ float2 g_sdst[N_NODES];                 // (sdst_h, sdst_l)
// W as B-operand [n=128][k=128] bf16 hi/lo, chunk-swizzled (ldmatrix-ready)
__device__ uint32_t g_Wblk_hi[8192];               // 32768 bytes
__device__ uint32_t g_Wblk_lo[8192];

// Swizzled byte offset in a [row][k] bf16 tile with 256B rows (128 k per row).
__device__ __forceinline__ uint32_t sw_off(int row, int k) {
    return (uint32_t)(row * 256 + ((((k >> 3) ^ (row & 7)) << 4) | ((k & 7) << 1)));
}

__device__ __forceinline__ uint32_t smem_u32(const void* p) {
    uint32_t a;
    asm("{ .reg .u64 t; cvta.to.shared.u64 t, %1; cvt.u32.u64 %0, t; }" : "=r"(a) : "l"(p));
    return a;
}

__device__ __forceinline__ void ldmatrix_x4(uint32_t* r, uint32_t addr) {
    asm volatile("ldmatrix.sync.aligned.m8n8.x4.shared.b16 {%0,%1,%2,%3}, [%4];"
                 : "=r"(r[0]), "=r"(r[1]), "=r"(r[2]), "=r"(r[3]) : "r"(addr));
}

__device__ __forceinline__ void mma_bf16(float* c, const uint32_t* a, uint32_t b0, uint32_t b1) {
    asm volatile(
        "mma.sync.aligned.m16n8k16.row.col.f32.bf16.bf16.f32 "
        "{%0,%1,%2,%3}, {%4,%5,%6,%7}, {%8,%9}, {%0,%1,%2,%3};"
        : "+f"(c[0]), "+f"(c[1]), "+f"(c[2]), "+f"(c[3])
        : "r"(a[0]), "r"(a[1]), "r"(a[2]), "r"(a[3]), "r"(b0), "r"(b1));
}

// ---------------------------------------------------------------------------
// K0: bake Wcat as B-operand [n][k] bf16 hi/lo, swizzled. B[n][k] = Wcat[k][n].
// ---------------------------------------------------------------------------
__global__ void k_wprep(const float* __restrict__ Wh, const float* __restrict__ Wl)
{
    int idx = blockIdx.x * blockDim.x + threadIdx.x;
    if (idx >= 128 * 64) return;
    int n = idx >> 6, kp = idx & 63, k = kp * 2;
    const float* Ws = (n < 64) ? Wh : Wl;
    int c = n & 63;
    float w0 = Ws[k * 64 + c];
    float w1 = Ws[(k + 1) * 64 + c];

    __nv_bfloat16 h0 = __float2bfloat16_rn(w0);
    __nv_bfloat16 h1 = __float2bfloat16_rn(w1);
    __nv_bfloat16 l0 = __float2bfloat16_rn(w0 - __bfloat162float(h0));
    __nv_bfloat16 l1 = __float2bfloat16_rn(w1 - __bfloat162float(h1));

    uint32_t hp = ((uint32_t)__bfloat16_as_ushort(h1) << 16) | __bfloat16_as_ushort(h0);
    uint32_t lp = ((uint32_t)__bfloat16_as_ushort(l1) << 16) | __bfloat16_as_ushort(l0);

    uint32_t off = sw_off(n, k);
    *(uint32_t*)((char*)g_Wblk_hi + off) = hp;
    *(uint32_t*)((char*)g_Wblk_lo + off) = lp;
}

// ---------------------------------------------------------------------------
// K1: mma.sync bf16 split GEMM. C[128x128] = A_tile @ Wcat (3 HMMA passes).
// ---------------------------------------------------------------------------
#define SM_AHI 0
#define SM_ALO 32768
#define SM_WHI 65536
#define SM_WLO 98304
#define SM_TOTAL 131072

__global__ __launch_bounds__(256, 1)
void k_gemm_mma(const float* __restrict__ A)
{
    extern __shared__ char smem[];
    const uint32_t sbase = smem_u32(smem);
    const int tid = threadIdx.x;
    const int wid = tid >> 5;
    const int lane = tid & 31;
    const int rowBase = blockIdx.x * 128;

    {
        const uint4* shi = (const uint4*)g_Wblk_hi;
        const uint4* slo = (const uint4*)g_Wblk_lo;
        uint4* dhi = (uint4*)(smem + SM_WHI);
        uint4* dlo = (uint4*)(smem + SM_WLO);
#pragma unroll
        for (int i = tid; i < 2048; i += 256) { dhi[i] = shi[i]; dlo[i] = slo[i]; }
    }

    for (int i = tid; i < 8192; i += 256) {
        int r = i >> 6, kp = i & 63, k = kp * 2;
        int node = rowBase + r;
        float2 v = make_float2(0.f, 0.f);
        if (node < N_NODES) v = *(const float2*)(A + (size_t)node * 128 + k);

        __nv_bfloat16 h0 = __float2bfloat16_rn(v.x);
        __nv_bfloat16 h1 = __float2bfloat16_rn(v.y);
        __nv_bfloat16 l0 = __float2bfloat16_rn(v.x - __bfloat162float(h0));
        __nv_bfloat16 l1 = __float2bfloat16_rn(v.y - __bfloat162float(h1));
        uint32_t hp = ((uint32_t)__bfloat16_as_ushort(h1) << 16) | __bfloat16_as_ushort(h0);
        uint32_t lp = ((uint32_t)__bfloat16_as_ushort(l1) << 16) | __bfloat16_as_ushort(l0);

        uint32_t off = sw_off(r, k);
        *(uint32_t*)(smem + SM_AHI + off) = hp;
        *(uint32_t*)(smem + SM_ALO + off) = lp;
    }
    __syncthreads();

    const int m_base = wid * 16;
    float c[16][4];
#pragma unroll
    for (int j = 0; j < 16; j++)
#pragma unroll
        for (int q = 0; q < 4; q++) c[j][q] = 0.f;

    const int g  = lane >> 3;
    const int rr = lane & 7;
    const int a_row = m_base + ((g & 1) << 3) + rr;
    const int a_kof = (g >> 1) << 3;
    const int b_nof = ((g >> 1) << 3) + rr;
    const int b_kof = (g & 1) << 3;

#pragma unroll
    for (int pass = 0; pass < 3; pass++) {
        const uint32_t aBase = sbase + ((pass == 2) ? SM_ALO : SM_AHI);
        const uint32_t bBase = sbase + ((pass == 1) ? SM_WLO : SM_WHI);
#pragma unroll
        for (int ks = 0; ks < 8; ks++) {
            const int kb = ks * 16;
            uint32_t a[4];
            ldmatrix_x4(a, aBase + sw_off(a_row, kb + a_kof));
#pragma unroll
            for (int nt = 0; nt < 8; nt++) {
                uint32_t b[4];
                ldmatrix_x4(b, bBase + sw_off(nt * 16 + b_nof, kb + b_kof));
                mma_bf16(c[2 * nt],     a, b[0], b[1]);
                mma_bf16(c[2 * nt + 1], a, b[2], b[3]);
            }
        }
    }

    const int row0 = rowBase + m_base + (lane >> 2);
    const int cb   = (lane & 3) * 2;
    if (row0 < N_NODES) {
        float* o = g_h + (size_t)row0 * 128;
#pragma unroll
        for (int j = 0; j < 16; j++)
            *(float2*)(o + j * 8 + cb) = make_float2(c[j][0], c[j][1]);
    }
    if (row0 + 8 < N_NODES) {
        float* o = g_h + (size_t)(row0 + 8) * 128;
#pragma unroll
        for (int j = 0; j < 16; j++)
            *(float2*)(o + j * 8 + cb) = make_float2(c[j][2], c[j][3]);
    }
}

// ---------------------------------------------------------------------------
// K2: per-node warp aggregation + attention scalars (staged gathers, MLP=8)
// ---------------------------------------------------------------------------
__global__ __launch_bounds__(256)
void k_agg(const int* __restrict__ dst_arr,
           const float* __restrict__ a_high,
           const float* __restrict__ a_low)
{
    const int warp = (blockIdx.x * blockDim.x + threadIdx.x) >> 5;
    const int lane = threadIdx.x & 31;
    if (warp >= N_NODES) return;
    const int i = warp;
    const unsigned FULL = 0xffffffffu;

    int d = 0;
    if (lane < DEG) d = dst_arr[i * DEG + lane];

    float4 self = *(const float4*)(g_h + (size_t)i * 128 + lane * 4);

    float4 s = make_float4(0.f, 0.f, 0.f, 0.f);
#pragma unroll
    for (int half = 0; half < 2; half++) {
        float4 v[8];
#pragma unroll
        for (int e = 0; e < 8; e++) {
            int de = __shfl_sync(FULL, d, half * 8 + e);
            v[e] = *(const float4*)(g_h + (size_t)de * 128 + lane * 4);
        }
#pragma unroll
        for (int e = 0; e < 8; e++) {
            s.x += v[e].x; s.y += v[e].y; s.z += v[e].z; s.w += v[e].w;
        }
    }

    float sgn = (lane < 16) ? 1.f : -1.f;
    float4 o;
    o.x = 16.f * self.x + sgn * s.x;
    o.y = 16.f * self.y + sgn * s.y;
    o.z = 16.f * self.z + sgn * s.z;
    o.w = 16.f * self.w + sgn * s.w;
    *(float4*)(g_hagg + (size_t)i * 128 + lane * 4) = o;

    const float* av = (lane < 16) ? a_high : a_low;
    const int j = (lane & 15) * 4;
    float4 a0 = *(const float4*)(av + j);
    float4 a1 = *(const float4*)(av + 64 + j);
    float p0 = self.x * a0.x + self.y * a0.y + self.z * a0.z + self.w * a0.w;
    float p1 = self.x * a1.x + self.y * a1.y + self.z * a1.z + self.w * a1.w;
#pragma unroll
    for (int off = 8; off; off >>= 1) {
        p0 += __shfl_xor_sync(FULL, p0, off);
        p1 += __shfl_xor_sync(FULL, p1, off);
    }
    // p0 = h . a_src, p1 = h . a_dst  (high on lane 0, low on lane 16)
    if (lane == 0)  g_ssrc[i].x = p0, g_sdst[i].x = p1;
    if (lane == 16) g_ssrc[i].y = p0, g_sdst[i].y = p1;
}

// ---------------------------------------------------------------------------
// K3: weighting + output (staged gathers, MLP=8; split scal arrays)
// ---------------------------------------------------------------------------
__global__ __launch_bounds__(256)
void k_out(const int* __restrict__ dst_arr, float* __restrict__ out)
{
    const int warp = (blockIdx.x * blockDim.x + threadIdx.x) >> 5;
    const int lane = threadIdx.x & 31;
    if (warp >= N_NODES) return;
    const int i = warp;
    const unsigned FULL = 0xffffffffu;

    int d = 0;
    if (lane < DEG) d = dst_arr[i * DEG + lane];

    float2 si = g_ssrc[i];   // broadcast

    float eh = 0.f, el = 0.f;
    if (lane < DEG) {
        float2 sd = g_sdst[d];
        float sh = si.x + sd.x;
        float sl = si.y + sd.y;
        float lh = sh > 0.f ? sh : ALPHA * sh;
        float ll = sl > 0.f ? sl : ALPHA * sl;
        eh = __expf(-lh);
        el = __expf(-ll);
    }

    float rh = eh, rl = el;
#pragma unroll
    for (int off = 8; off; off >>= 1) {
        rh += __shfl_xor_sync(FULL, rh, off);
        rl += __shfl_xor_sync(FULL, rl, off);
    }
    rh = __shfl_sync(FULL, rh, 0);
    rl = __shfl_sync(FULL, rl, 0);

    float ehc = fminf(eh, 6.f);
    float elc = fminf(el, 6.f);

    float4 acc = make_float4(0.f, 0.f, 0.f, 0.f);
#pragma unroll
    for (int half = 0; half < 2; half++) {
        float4 v[8];
        float  w[8];
#pragma unroll
        for (int e = 0; e < 8; e++) {
            int   de = __shfl_sync(FULL, d, half * 8 + e);
            float wh = __shfl_sync(FULL, ehc, half * 8 + e);
            float wl = __shfl_sync(FULL, elc, half * 8 + e);
            w[e] = (lane < 16) ? wh : wl;
            v[e] = *(const float4*)(g_hagg + (size_t)de * 128 + lane * 4);
        }
#pragma unroll
        for (int e = 0; e < 8; e++) {
            acc.x += w[e] * v[e].x; acc.y += w[e] * v[e].y;
            acc.z += w[e] * v[e].z; acc.w += w[e] * v[e].w;
        }
    }

    float lx = __shfl_xor_sync(FULL, acc.x, 16);
    float ly = __shfl_xor_sync(FULL, acc.y, 16);
    float lz = __shfl_xor_sync(FULL, acc.z, 16);
    float lw = __shfl_xor_sync(FULL, acc.w, 16);

    if (lane < 16) {
        float irh = 1.f / rh, irl = 1.f / rl;
        float4 r;
        r.x = 0.5f * (acc.x * irh + lx * irl);
        r.y = 0.5f * (acc.y * irh + ly * irl);
        r.z = 0.5f * (acc.z * irh + lz * irl);
        r.w = 0.5f * (acc.w * irh + lw * irl);
        r.x = fminf(fmaxf(r.x, 0.f), 6.f);
        r.y = fminf(fmaxf(r.y, 0.f), 6.f);
        r.z = fminf(fmaxf(r.z, 0.f), 6.f);
        r.w = fminf(fmaxf(r.w, 0.f), 6.f);
        *(float4*)(out + (size_t)i * 64 + lane * 4) = r;
    }
}

// ---------------------------------------------------------------------------
extern "C" void kernel_launch(void* const* d_in, const int* in_sizes, int n_in,
                              void* d_out, int out_size)
{
    const float* input = (const float*)d_in[0];
    const int*   edge  = (const int*)  d_in[1];
    const float* Wh    = (const float*)d_in[2];
    const float* Wl    = (const float*)d_in[3];
    const float* ah    = (const float*)d_in[4];
    const float* al    = (const float*)d_in[5];
    float* out = (float*)d_out;

    const int* dst = edge + E_EDGES;

    cudaFuncSetAttribute(k_gemm_mma, cudaFuncAttributeMaxDynamicSharedMemorySize, SM_TOTAL);

    k_wprep<<<32, 256>>>(Wh, Wl);

    const int gemmBlocks = (N_NODES + 127) / 128;   // 782
    k_gemm_mma<<<gemmBlocks, 256, SM_TOTAL>>>(input);

    const int warpBlocks = (N_NODES + 7) / 8;
    k_agg<<<warpBlocks, 256>>>(dst, ah, al);
    k_out<<<warpBlocks, 256>>>(dst, out);
}

// round 5
// speedup vs baseline: 1.4270x; 1.2029x over previous
#include <cuda_runtime.h>
#include <cuda_bf16.h>
#include <cuda_fp16.h>
#include <cstdint>

#define N_NODES 100000
#define DEG     16
#define E_EDGES (N_NODES * DEG)
#define ALPHA   0.2f

// Scratch (static __device__ — no allocs allowed)
__device__ __half  g_h16   [(size_t)N_NODES * 128];  // [h_high(64) | h_low(64)] fp16
__device__ __half  g_hagg16[(size_t)N_NODES * 128];  // [hagg_high | hagg_low]  fp16
__device__ float2  g_ssrc[N_NODES];                  // (ssrc_h, ssrc_l)  fp32
__device__ float2  g_sdst[N_NODES];                  // (sdst_h, sdst_l)  fp32
// W as B-operand [n=128][k=128] bf16 hi/lo, chunk-swizzled (ldmatrix-ready)
__device__ uint32_t g_Wblk_hi[8192];
__device__ uint32_t g_Wblk_lo[8192];

__device__ __forceinline__ uint32_t sw_off(int row, int k) {
    return (uint32_t)(row * 256 + ((((k >> 3) ^ (row & 7)) << 4) | ((k & 7) << 1)));
}

__device__ __forceinline__ uint32_t smem_u32(const void* p) {
    uint32_t a;
    asm("{ .reg .u64 t; cvta.to.shared.u64 t, %1; cvt.u32.u64 %0, t; }" : "=r"(a) : "l"(p));
    return a;
}

__device__ __forceinline__ void ldmatrix_x4(uint32_t* r, uint32_t addr) {
    asm volatile("ldmatrix.sync.aligned.m8n8.x4.shared.b16 {%0,%1,%2,%3}, [%4];"
                 : "=r"(r[0]), "=r"(r[1]), "=r"(r[2]), "=r"(r[3]) : "r"(addr));
}

__device__ __forceinline__ void mma_bf16(float* c, const uint32_t* a, uint32_t b0, uint32_t b1) {
    asm volatile(
        "mma.sync.aligned.m16n8k16.row.col.f32.bf16.bf16.f32 "
        "{%0,%1,%2,%3}, {%4,%5,%6,%7}, {%8,%9}, {%0,%1,%2,%3};"
        : "+f"(c[0]), "+f"(c[1]), "+f"(c[2]), "+f"(c[3])
        : "r"(a[0]), "r"(a[1]), "r"(a[2]), "r"(a[3]), "r"(b0), "r"(b1));
}

// ---------------------------------------------------------------------------
// K0: bake Wcat as B-operand [n][k] bf16 hi/lo, swizzled. B[n][k] = Wcat[k][n].
// ---------------------------------------------------------------------------
__global__ void k_wprep(const float* __restrict__ Wh, const float* __restrict__ Wl)
{
    int idx = blockIdx.x * blockDim.x + threadIdx.x;
    if (idx >= 128 * 64) return;
    int n = idx >> 6, kp = idx & 63, k = kp * 2;
    const float* Ws = (n < 64) ? Wh : Wl;
    int c = n & 63;
    float w0 = Ws[k * 64 + c];
    float w1 = Ws[(k + 1) * 64 + c];

    __nv_bfloat16 h0 = __float2bfloat16_rn(w0);
    __nv_bfloat16 h1 = __float2bfloat16_rn(w1);
    __nv_bfloat16 l0 = __float2bfloat16_rn(w0 - __bfloat162float(h0));
    __nv_bfloat16 l1 = __float2bfloat16_rn(w1 - __bfloat162float(h1));

    uint32_t hp = ((uint32_t)__bfloat16_as_ushort(h1) << 16) | __bfloat16_as_ushort(h0);
    uint32_t lp = ((uint32_t)__bfloat16_as_ushort(l1) << 16) | __bfloat16_as_ushort(l0);

    uint32_t off = sw_off(n, k);
    *(uint32_t*)((char*)g_Wblk_hi + off) = hp;
    *(uint32_t*)((char*)g_Wblk_lo + off) = lp;
}

// ---------------------------------------------------------------------------
// K1: mma.sync bf16 split GEMM + fused epilogue:
//   - writes h as fp16 (g_h16)
//   - computes attention scalars in fp32 from the register accumulators
// ---------------------------------------------------------------------------
#define SM_AHI 0
#define SM_ALO 32768
#define SM_WHI 65536
#define SM_WLO 98304
#define SM_TOTAL 131072

__global__ __launch_bounds__(256, 1)
void k_gemm_mma(const float* __restrict__ A,
                const float* __restrict__ ah,
                const float* __restrict__ al)
{
    extern __shared__ char smem[];
    const uint32_t sbase = smem_u32(smem);
    const int tid = threadIdx.x;
    const int wid = tid >> 5;
    const int lane = tid & 31;
    const int rowBase = blockIdx.x * 128;

    {
        const uint4* shi = (const uint4*)g_Wblk_hi;
        const uint4* slo = (const uint4*)g_Wblk_lo;
        uint4* dhi = (uint4*)(smem + SM_WHI);
        uint4* dlo = (uint4*)(smem + SM_WLO);
#pragma unroll
        for (int i = tid; i < 2048; i += 256) { dhi[i] = shi[i]; dlo[i] = slo[i]; }
    }

    for (int i = tid; i < 8192; i += 256) {
        int r = i >> 6, kp = i & 63, k = kp * 2;
        int node = rowBase + r;
        float2 v = make_float2(0.f, 0.f);
        if (node < N_NODES) v = *(const float2*)(A + (size_t)node * 128 + k);

        __nv_bfloat16 h0 = __float2bfloat16_rn(v.x);
        __nv_bfloat16 h1 = __float2bfloat16_rn(v.y);
        __nv_bfloat16 l0 = __float2bfloat16_rn(v.x - __bfloat162float(h0));
        __nv_bfloat16 l1 = __float2bfloat16_rn(v.y - __bfloat162float(h1));
        uint32_t hp = ((uint32_t)__bfloat16_as_ushort(h1) << 16) | __bfloat16_as_ushort(h0);
        uint32_t lp = ((uint32_t)__bfloat16_as_ushort(l1) << 16) | __bfloat16_as_ushort(l0);

        uint32_t off = sw_off(r, k);
        *(uint32_t*)(smem + SM_AHI + off) = hp;
        *(uint32_t*)(smem + SM_ALO + off) = lp;
    }
    __syncthreads();

    const int m_base = wid * 16;
    float c[16][4];
#pragma unroll
    for (int j = 0; j < 16; j++)
#pragma unroll
        for (int q = 0; q < 4; q++) c[j][q] = 0.f;

    const int g  = lane >> 3;
    const int rr = lane & 7;
    const int a_row = m_base + ((g & 1) << 3) + rr;
    const int a_kof = (g >> 1) << 3;
    const int b_nof = ((g >> 1) << 3) + rr;
    const int b_kof = (g & 1) << 3;

#pragma unroll
    for (int pass = 0; pass < 3; pass++) {
        const uint32_t aBase = sbase + ((pass == 2) ? SM_ALO : SM_AHI);
        const uint32_t bBase = sbase + ((pass == 1) ? SM_WLO : SM_WHI);
#pragma unroll
        for (int ks = 0; ks < 8; ks++) {
            const int kb = ks * 16;
            uint32_t a[4];
            ldmatrix_x4(a, aBase + sw_off(a_row, kb + a_kof));
#pragma unroll
            for (int nt = 0; nt < 8; nt++) {
                uint32_t b[4];
                ldmatrix_x4(b, bBase + sw_off(nt * 16 + b_nof, kb + b_kof));
                mma_bf16(c[2 * nt],     a, b[0], b[1]);
                mma_bf16(c[2 * nt + 1], a, b[2], b[3]);
            }
        }
    }

    // --- writeout h as fp16 ---
    const int row0 = rowBase + m_base + (lane >> 2);
    const int cb   = (lane & 3) * 2;
    if (row0 < N_NODES) {
        __half* o = g_h16 + (size_t)row0 * 128;
#pragma unroll
        for (int j = 0; j < 16; j++)
            *(__half2*)(o + j * 8 + cb) = __floats2half2_rn(c[j][0], c[j][1]);
    }
    if (row0 + 8 < N_NODES) {
        __half* o = g_h16 + (size_t)(row0 + 8) * 128;
#pragma unroll
        for (int j = 0; j < 16; j++)
            *(__half2*)(o + j * 8 + cb) = __floats2half2_rn(c[j][2], c[j][3]);
    }

    // --- attention scalars (fp32, from register accumulators) ---
    // cols 8j+cb, 8j+cb+1. j<8 -> high half (a_high), j>=8 -> low half (a_low).
    float ssh0 = 0.f, sdh0 = 0.f, ssl0 = 0.f, sdl0 = 0.f;   // row0
    float ssh1 = 0.f, sdh1 = 0.f, ssl1 = 0.f, sdl1 = 0.f;   // row0+8
#pragma unroll
    for (int j = 0; j < 8; j++) {
        int c0 = j * 8 + cb;
        float2 as = *(const float2*)(ah + c0);        // a_src_high
        float2 ad = *(const float2*)(ah + 64 + c0);   // a_dst_high
        ssh0 += c[j][0] * as.x + c[j][1] * as.y;
        sdh0 += c[j][0] * ad.x + c[j][1] * ad.y;
        ssh1 += c[j][2] * as.x + c[j][3] * as.y;
        sdh1 += c[j][2] * ad.x + c[j][3] * ad.y;
    }
#pragma unroll
    for (int j = 8; j < 16; j++) {
        int c0 = (j - 8) * 8 + cb;
        float2 as = *(const float2*)(al + c0);        // a_src_low
        float2 ad = *(const float2*)(al + 64 + c0);   // a_dst_low
        ssl0 += c[j][0] * as.x + c[j][1] * as.y;
        sdl0 += c[j][0] * ad.x + c[j][1] * ad.y;
        ssl1 += c[j][2] * as.x + c[j][3] * as.y;
        sdl1 += c[j][2] * ad.x + c[j][3] * ad.y;
    }
    const unsigned FULL = 0xffffffffu;
#pragma unroll
    for (int off = 1; off <= 2; off <<= 1) {
        ssh0 += __shfl_xor_sync(FULL, ssh0, off);
        sdh0 += __shfl_xor_sync(FULL, sdh0, off);
        ssl0 += __shfl_xor_sync(FULL, ssl0, off);
        sdl0 += __shfl_xor_sync(FULL, sdl0, off);
        ssh1 += __shfl_xor_sync(FULL, ssh1, off);
        sdh1 += __shfl_xor_sync(FULL, sdh1, off);
        ssl1 += __shfl_xor_sync(FULL, ssl1, off);
        sdl1 += __shfl_xor_sync(FULL, sdl1, off);
    }
    if ((lane & 3) == 0) {
        if (row0 < N_NODES) {
            g_ssrc[row0] = make_float2(ssh0, ssl0);
            g_sdst[row0] = make_float2(sdh0, sdl0);
        }
        if (row0 + 8 < N_NODES) {
            g_ssrc[row0 + 8] = make_float2(ssh1, ssl1);
            g_sdst[row0 + 8] = make_float2(sdh1, sdl1);
        }
    }
}

// ---------------------------------------------------------------------------
// K2: per-node warp aggregation (fp16 gather, 8B/lane)
// ---------------------------------------------------------------------------
__global__ __launch_bounds__(256)
void k_agg(const int* __restrict__ dst_arr)
{
    const int warp = (blockIdx.x * blockDim.x + threadIdx.x) >> 5;
    const int lane = threadIdx.x & 31;
    if (warp >= N_NODES) return;
    const int i = warp;
    const unsigned FULL = 0xffffffffu;

    int d = 0;
    if (lane < DEG) d = dst_arr[i * DEG + lane];

    // lane covers fp16 elements 4*lane .. 4*lane+3
    uint2 sraw = *(const uint2*)(g_h16 + (size_t)i * 128 + lane * 4);
    float2 s0 = __half22float2(*(__half2*)&sraw.x);
    float2 s1 = __half22float2(*(__half2*)&sraw.y);

    float4 s = make_float4(0.f, 0.f, 0.f, 0.f);
#pragma unroll
    for (int e = 0; e < DEG; e++) {
        int de = __shfl_sync(FULL, d, e);
        uint2 raw = *(const uint2*)(g_h16 + (size_t)de * 128 + lane * 4);
        float2 f0 = __half22float2(*(__half2*)&raw.x);
        float2 f1 = __half22float2(*(__half2*)&raw.y);
        s.x += f0.x; s.y += f0.y; s.z += f1.x; s.w += f1.y;
    }

    float sgn = (lane < 16) ? 1.f : -1.f;
    __half2 o0 = __floats2half2_rn(16.f * s0.x + sgn * s.x, 16.f * s0.y + sgn * s.y);
    __half2 o1 = __floats2half2_rn(16.f * s1.x + sgn * s.z, 16.f * s1.y + sgn * s.w);
    uint2 ov;
    ov.x = *(uint32_t*)&o0;
    ov.y = *(uint32_t*)&o1;
    *(uint2*)(g_hagg16 + (size_t)i * 128 + lane * 4) = ov;
}

// ---------------------------------------------------------------------------
// K3: weighting + output (fp16 gather, 8B/lane)
// ---------------------------------------------------------------------------
__global__ __launch_bounds__(256)
void k_out(const int* __restrict__ dst_arr, float* __restrict__ out)
{
    const int warp = (blockIdx.x * blockDim.x + threadIdx.x) >> 5;
    const int lane = threadIdx.x & 31;
    if (warp >= N_NODES) return;
    const int i = warp;
    const unsigned FULL = 0xffffffffu;

    int d = 0;
    if (lane < DEG) d = dst_arr[i * DEG + lane];

    float2 si = g_ssrc[i];   // broadcast

    float eh = 0.f, el = 0.f;
    if (lane < DEG) {
        float2 sd = g_sdst[d];
        float sh = si.x + sd.x;
        float sl = si.y + sd.y;
        float lh = sh > 0.f ? sh : ALPHA * sh;
        float ll = sl > 0.f ? sl : ALPHA * sl;
        eh = __expf(-lh);
        el = __expf(-ll);
    }

    float rh = eh, rl = el;
#pragma unroll
    for (int off = 8; off; off >>= 1) {
        rh += __shfl_xor_sync(FULL, rh, off);
        rl += __shfl_xor_sync(FULL, rl, off);
    }
    rh = __shfl_sync(FULL, rh, 0);
    rl = __shfl_sync(FULL, rl, 0);

    float ehc = fminf(eh, 6.f);
    float elc = fminf(el, 6.f);

    float4 acc = make_float4(0.f, 0.f, 0.f, 0.f);
#pragma unroll
    for (int e = 0; e < DEG; e++) {
        int   de = __shfl_sync(FULL, d,   e);
        float wh = __shfl_sync(FULL, ehc, e);
        float wl = __shfl_sync(FULL, elc, e);
        float w  = (lane < 16) ? wh : wl;
        uint2 raw = *(const uint2*)(g_hagg16 + (size_t)de * 128 + lane * 4);
        float2 f0 = __half22float2(*(__half2*)&raw.x);
        float2 f1 = __half22float2(*(__half2*)&raw.y);
        acc.x += w * f0.x; acc.y += w * f0.y;
        acc.z += w * f1.x; acc.w += w * f1.y;
    }

    float lx = __shfl_xor_sync(FULL, acc.x, 16);
    float ly = __shfl_xor_sync(FULL, acc.y, 16);
    float lz = __shfl_xor_sync(FULL, acc.z, 16);
    float lw = __shfl_xor_sync(FULL, acc.w, 16);

    if (lane < 16) {
        float irh = 1.f / rh, irl = 1.f / rl;
        float4 r;
        r.x = 0.5f * (acc.x * irh + lx * irl);
        r.y = 0.5f * (acc.y * irh + ly * irl);
        r.z = 0.5f * (acc.z * irh + lz * irl);
        r.w = 0.5f * (acc.w * irh + lw * irl);
        r.x = fminf(fmaxf(r.x, 0.f), 6.f);
        r.y = fminf(fmaxf(r.y, 0.f), 6.f);
        r.z = fminf(fmaxf(r.z, 0.f), 6.f);
        r.w = fminf(fmaxf(r.w, 0.f), 6.f);
        *(float4*)(out + (size_t)i * 64 + lane * 4) = r;
    }
}

// ---------------------------------------------------------------------------
extern "C" void kernel_launch(void* const* d_in, const int* in_sizes, int n_in,
                              void* d_out, int out_size)
{
    const float* input = (const float*)d_in[0];
    const int*   edge  = (const int*)  d_in[1];
    const float* Wh    = (const float*)d_in[2];
    const float* Wl    = (const float*)d_in[3];
    const float* ah    = (const float*)d_in[4];
    const float* al    = (const float*)d_in[5];
    float* out = (float*)d_out;

    const int* dst = edge + E_EDGES;

    cudaFuncSetAttribute(k_gemm_mma, cudaFuncAttributeMaxDynamicSharedMemorySize, SM_TOTAL);

    k_wprep<<<32, 256>>>(Wh, Wl);

    const int gemmBlocks = (N_NODES + 127) / 128;   // 782
    k_gemm_mma<<<gemmBlocks, 256, SM_TOTAL>>>(input, ah, al);

    const int warpBlocks = (N_NODES + 7) / 8;
    k_agg<<<warpBlocks, 256>>>(dst);
    k_out<<<warpBlocks, 256>>>(dst, out);
}